// round 2
// baseline (speedup 1.0000x reference)
#include <cuda_runtime.h>
#include <math.h>

#define NN      50000
#define E_BASE  800000
#define E_TOT   850000   // + self loops
#define FEAT    128
#define HID     128
#define NHEAD   8

// ---------------- scratch (device globals; no allocation) ----------------
__device__ float g_h  [NN * HID];   // per-layer transformed features
__device__ float g_x2 [NN * HID];   // layer-1 output (input to layer 2)
__device__ float g_as [NN * NHEAD];
__device__ float g_ad [NN * NHEAD];
__device__ float g_wa [128 * 16];   // [k][0..7]=W@a_src per head, [8..15]=W@a_dst
__device__ int   g_cnt[NN];
__device__ int   g_off[NN + 1];
__device__ int   g_rank[E_TOT];     // per-edge rank within its dst bucket
__device__ int   g_csr[E_TOT];      // src node per CSR slot (grouped by dst)

// ---------------- CSR build ----------------
__global__ void zero_kernel() {
    int i = blockIdx.x * blockDim.x + threadIdx.x;
    if (i < NN) g_cnt[i] = 0;
}

// count per-dst degree AND record each edge's rank within its dst bucket
__global__ void count_kernel(const int* __restrict__ ei) {
    int i = blockIdx.x * blockDim.x + threadIdx.x;
    if (i >= E_TOT) return;
    int d = (i < E_BASE) ? ei[E_BASE + i] : (i - E_BASE);
    g_rank[i] = atomicAdd(&g_cnt[d], 1);
}

// thread-coarsened exclusive scan: 1024 threads x CHUNK contiguous elements
#define SCAN_CHUNK 49   // ceil(50000/1024)
__global__ void scan_kernel() {
    __shared__ int warp_sums[32];
    int t = threadIdx.x;              // 1024
    int lane = t & 31, w = t >> 5;
    int base = t * SCAN_CHUNK;

    // local sum of this thread's chunk
    int local = 0;
    #pragma unroll 7
    for (int j = 0; j < SCAN_CHUNK; ++j) {
        int i = base + j;
        if (i < NN) local += g_cnt[i];
    }
    // block exclusive scan of 1024 local sums
    int x = local;
    #pragma unroll
    for (int o = 1; o < 32; o <<= 1) {
        int y = __shfl_up_sync(0xffffffffu, x, o);
        if (lane >= o) x += y;
    }
    if (lane == 31) warp_sums[w] = x;
    __syncthreads();
    if (w == 0) {
        int s = (lane < 32) ? warp_sums[lane] : 0;
        #pragma unroll
        for (int o = 1; o < 32; o <<= 1) {
            int y = __shfl_up_sync(0xffffffffu, s, o);
            if (lane >= o) s += y;
        }
        warp_sums[lane] = s;
    }
    __syncthreads();
    int excl = x - local + ((w > 0) ? warp_sums[w - 1] : 0);

    // write running offsets over the chunk
    int run = excl;
    #pragma unroll 7
    for (int j = 0; j < SCAN_CHUNK; ++j) {
        int i = base + j;
        if (i < NN) { g_off[i] = run; run += g_cnt[i]; }
    }
    if (t == 1023) g_off[NN] = run;   // last thread's running total == E_TOT
}

// atomic-free scatter using precomputed ranks
__global__ void scatter_kernel(const int* __restrict__ ei) {
    int i = blockIdx.x * blockDim.x + threadIdx.x;
    if (i >= E_TOT) return;
    int s, d;
    if (i < E_BASE) { s = ei[i]; d = ei[E_BASE + i]; }
    else            { s = d = i - E_BASE; }
    g_csr[g_off[d] + g_rank[i]] = s;
}

// ---------------- wa = W @ a (per head), folded attention logit weights ----
__global__ void wa_kernel(const float* __restrict__ W,
                          const float* __restrict__ a_src,
                          const float* __restrict__ a_dst) {
    __shared__ float as[128], ad[128];
    int t = threadIdx.x;  // 128
    as[t] = a_src[t];
    ad[t] = a_dst[t];
    __syncthreads();
    int k = t;
    #pragma unroll
    for (int h = 0; h < 8; h++) {
        float s = 0.f, d = 0.f;
        #pragma unroll
        for (int c = 0; c < 16; c++) {
            float w = W[k * 128 + h * 16 + c];
            s += w * as[h * 16 + c];
            d += w * ad[h * 16 + c];
        }
        g_wa[k * 16 + h]     = s;
        g_wa[k * 16 + 8 + h] = d;
    }
}

// ---------------- GEMM: [rows x 128] @ [128 x 144] -> h, alpha_s, alpha_d ----
#define WST 144
#define XST 132
#define GEMM_SMEM ((128 * WST + 64 * XST) * 4)   // 107520 B

__global__ void __launch_bounds__(256, 2)
gemm_kernel(const float* __restrict__ X, const float* __restrict__ W) {
    extern __shared__ float sm[];
    float* Wsh = sm;                 // 128 x 144 (stride WST)
    float* xs  = sm + 128 * WST;     // 64 x 128 (stride XST)

    int tid = threadIdx.x;           // 256
    int row0 = blockIdx.x * 64;

    // load W (128x128)
    for (int i = tid * 4; i < 128 * 128; i += 1024) {
        float4 w = *(const float4*)(W + i);
        int k = i >> 7, c = i & 127;
        *(float4*)(Wsh + k * WST + c) = w;
    }
    // load wa cols (128 x 16)
    for (int i = tid; i < 128 * 16; i += 256) {
        Wsh[(i >> 4) * WST + 128 + (i & 15)] = g_wa[i];
    }
    // load X rows
    for (int i = tid * 4; i < 64 * 128; i += 1024) {
        int r = i >> 7, c = i & 127;
        int gr = row0 + r;
        float4 v = make_float4(0.f, 0.f, 0.f, 0.f);
        if (gr < NN) v = *(const float4*)(X + gr * FEAT + c);
        *(float4*)(xs + r * XST + c) = v;
    }
    __syncthreads();

    int ty = tid >> 4, tx = tid & 15;   // 16x16; thread tile 4 rows x 9 cols
    float acc[4][9];
    #pragma unroll
    for (int i = 0; i < 4; i++)
        #pragma unroll
        for (int j = 0; j < 9; j++) acc[i][j] = 0.f;

    #pragma unroll 8
    for (int k = 0; k < 128; ++k) {
        float a0 = xs[(ty * 4 + 0) * XST + k];
        float a1 = xs[(ty * 4 + 1) * XST + k];
        float a2 = xs[(ty * 4 + 2) * XST + k];
        float a3 = xs[(ty * 4 + 3) * XST + k];
        const float* wr = Wsh + k * WST + tx;
        #pragma unroll
        for (int j = 0; j < 9; ++j) {
            float b = wr[16 * j];
            acc[0][j] += a0 * b;
            acc[1][j] += a1 * b;
            acc[2][j] += a2 * b;
            acc[3][j] += a3 * b;
        }
    }

    #pragma unroll
    for (int i = 0; i < 4; ++i) {
        int gr = row0 + ty * 4 + i;
        if (gr >= NN) continue;
        float* hrow = g_h + gr * HID;
        #pragma unroll
        for (int j = 0; j < 8; ++j) hrow[tx + 16 * j] = acc[i][j];
        if (tx < 8) g_as[gr * 8 + tx]     = acc[i][8];
        else        g_ad[gr * 8 + tx - 8] = acc[i][8];
    }
}

// ---------------- fused GAT aggregation: warp per dst node -----------------
// out[d,:] = elu( (sum_e exp(lrelu(as[src]+ad[d])) * h[src]) / sum_e exp(...) + b )
__global__ void msg_kernel(const float* __restrict__ bias, float* __restrict__ out) {
    int gwarp = (blockIdx.x * blockDim.x + threadIdx.x) >> 5;
    int lane = threadIdx.x & 31;
    if (gwarp >= NN) return;
    int d = gwarp;
    int head = lane >> 2;                    // 4 lanes per head (16 dims / 4)
    float ad_h = g_ad[d * 8 + head];
    int beg = g_off[d], end = g_off[d + 1];

    float4 acc = make_float4(0.f, 0.f, 0.f, 0.f);
    float ssum = 0.f;
    int col = lane << 2;

    int i = beg;
    // unrolled-by-2 with batched loads for 2x MLP
    for (; i + 2 <= end; i += 2) {
        int s0 = __ldg(&g_csr[i]);
        int s1 = __ldg(&g_csr[i + 1]);
        float as0 = __ldg(&g_as[s0 * 8 + head]);
        float as1 = __ldg(&g_as[s1 * 8 + head]);
        float4 h0 = *(const float4*)(g_h + s0 * 128 + col);
        float4 h1 = *(const float4*)(g_h + s1 * 128 + col);
        float v0 = as0 + ad_h; v0 = (v0 > 0.f) ? v0 : 0.2f * v0;
        float v1 = as1 + ad_h; v1 = (v1 > 0.f) ? v1 : 0.2f * v1;
        float e0 = __expf(v0);
        float e1 = __expf(v1);
        acc.x += e0 * h0.x + e1 * h1.x;
        acc.y += e0 * h0.y + e1 * h1.y;
        acc.z += e0 * h0.z + e1 * h1.z;
        acc.w += e0 * h0.w + e1 * h1.w;
        ssum += e0 + e1;
    }
    if (i < end) {
        int s0 = __ldg(&g_csr[i]);
        float as0 = __ldg(&g_as[s0 * 8 + head]);
        float4 h0 = *(const float4*)(g_h + s0 * 128 + col);
        float v0 = as0 + ad_h; v0 = (v0 > 0.f) ? v0 : 0.2f * v0;
        float e0 = __expf(v0);
        acc.x += e0 * h0.x;
        acc.y += e0 * h0.y;
        acc.z += e0 * h0.z;
        acc.w += e0 * h0.w;
        ssum += e0;
    }

    float inv = 1.f / (ssum + 1e-16f);
    float4 bb = *(const float4*)(bias + col);
    float4 o;
    float t;
    t = acc.x * inv + bb.x; o.x = (t > 0.f) ? t : expm1f(t);
    t = acc.y * inv + bb.y; o.y = (t > 0.f) ? t : expm1f(t);
    t = acc.z * inv + bb.z; o.z = (t > 0.f) ? t : expm1f(t);
    t = acc.w * inv + bb.w; o.w = (t > 0.f) ? t : expm1f(t);
    *(float4*)(out + d * 128 + col) = o;
}

// ---------------- launch ----------------
extern "C" void kernel_launch(void* const* d_in, const int* in_sizes, int n_in,
                              void* d_out, int out_size) {
    const float* x   = (const float*)d_in[0];
    const int*   ei  = (const int*)  d_in[1];
    const float* W1  = (const float*)d_in[2];
    const float* as1 = (const float*)d_in[3];
    const float* ad1 = (const float*)d_in[4];
    const float* b1  = (const float*)d_in[5];
    const float* W2  = (const float*)d_in[6];
    const float* as2 = (const float*)d_in[7];
    const float* ad2 = (const float*)d_in[8];
    const float* b2  = (const float*)d_in[9];
    float* out = (float*)d_out;

    cudaFuncSetAttribute(gemm_kernel,
                         cudaFuncAttributeMaxDynamicSharedMemorySize, GEMM_SMEM);

    void* p_x2 = nullptr;
    cudaGetSymbolAddress(&p_x2, g_x2);
    float* x2 = (float*)p_x2;

    // CSR build (graph identical for both layers)
    zero_kernel   <<<(NN + 255) / 256, 256>>>();
    count_kernel  <<<(E_TOT + 255) / 256, 256>>>(ei);
    scan_kernel   <<<1, 1024>>>();
    scatter_kernel<<<(E_TOT + 255) / 256, 256>>>(ei);

    int gemm_grid = (NN + 63) / 64;
    int msg_grid  = (NN * 32 + 255) / 256;

    // layer 1
    wa_kernel  <<<1, 128>>>(W1, as1, ad1);
    gemm_kernel<<<gemm_grid, 256, GEMM_SMEM>>>(x, W1);   // launch #6 -> ncu target
    msg_kernel <<<msg_grid, 256>>>(b1, x2);              // fused bias + elu

    // layer 2
    wa_kernel  <<<1, 128>>>(W2, as2, ad2);
    gemm_kernel<<<gemm_grid, 256, GEMM_SMEM>>>(x2, W2);
    msg_kernel <<<msg_grid, 256>>>(b2, out);             // fused bias + elu -> final
}

// round 3
// speedup vs baseline: 1.0563x; 1.0563x over previous
#include <cuda_runtime.h>
#include <math.h>

#define NN      50000
#define E_BASE  800000
#define E_TOT   850000   // + self loops
#define FEAT    128
#define HID     128
#define NHEAD   8

typedef unsigned long long ull;

// ---------------- scratch (device globals; no allocation) ----------------
__device__ float g_h  [NN * HID];   // per-layer transformed features
__device__ float g_x2 [NN * HID];   // layer-1 output (input to layer 2)
__device__ float g_as [NN * NHEAD];
__device__ float g_ad [NN * NHEAD];
__device__ float g_wa [128 * 16];   // [k][0..7]=W@a_src per head, [8..15]=W@a_dst
__device__ int   g_cnt[NN];
__device__ int   g_off[NN + 1];
__device__ int   g_rank[E_TOT];     // per-edge rank within its dst bucket
__device__ int   g_csr[E_TOT];      // src node per CSR slot (grouped by dst)

// packed f32x2 FMA: d.lo += a.lo*b.lo ; d.hi += a.hi*b.hi  (2x fp32 FMA tput)
__device__ __forceinline__ void ffma2(ull& d, ull a, ull b) {
    asm("fma.rn.f32x2 %0, %1, %2, %0;" : "+l"(d) : "l"(a), "l"(b));
}

// ---------------- CSR build ----------------
__global__ void zero_kernel() {
    int i = blockIdx.x * blockDim.x + threadIdx.x;
    if (i < NN) g_cnt[i] = 0;
}

// count per-dst degree AND record each edge's rank within its dst bucket
__global__ void count_kernel(const int* __restrict__ ei) {
    int i = blockIdx.x * blockDim.x + threadIdx.x;
    if (i >= E_TOT) return;
    int d = (i < E_BASE) ? ei[E_BASE + i] : (i - E_BASE);
    g_rank[i] = atomicAdd(&g_cnt[d], 1);
}

// thread-coarsened exclusive scan: 1024 threads x CHUNK contiguous elements
#define SCAN_CHUNK 49   // ceil(50000/1024)
__global__ void scan_kernel() {
    __shared__ int warp_sums[32];
    int t = threadIdx.x;              // 1024
    int lane = t & 31, w = t >> 5;
    int base = t * SCAN_CHUNK;

    int local = 0;
    #pragma unroll 7
    for (int j = 0; j < SCAN_CHUNK; ++j) {
        int i = base + j;
        if (i < NN) local += g_cnt[i];
    }
    int x = local;
    #pragma unroll
    for (int o = 1; o < 32; o <<= 1) {
        int y = __shfl_up_sync(0xffffffffu, x, o);
        if (lane >= o) x += y;
    }
    if (lane == 31) warp_sums[w] = x;
    __syncthreads();
    if (w == 0) {
        int s = warp_sums[lane];
        #pragma unroll
        for (int o = 1; o < 32; o <<= 1) {
            int y = __shfl_up_sync(0xffffffffu, s, o);
            if (lane >= o) s += y;
        }
        warp_sums[lane] = s;
    }
    __syncthreads();
    int excl = x - local + ((w > 0) ? warp_sums[w - 1] : 0);

    int run = excl;
    #pragma unroll 7
    for (int j = 0; j < SCAN_CHUNK; ++j) {
        int i = base + j;
        if (i < NN) { g_off[i] = run; run += g_cnt[i]; }
    }
    if (t == 1023) g_off[NN] = run;
}

// atomic-free scatter using precomputed ranks
__global__ void scatter_kernel(const int* __restrict__ ei) {
    int i = blockIdx.x * blockDim.x + threadIdx.x;
    if (i >= E_TOT) return;
    int s, d;
    if (i < E_BASE) { s = ei[i]; d = ei[E_BASE + i]; }
    else            { s = d = i - E_BASE; }
    g_csr[g_off[d] + g_rank[i]] = s;
}

// ---------------- wa = W @ a (per head), folded attention logit weights ----
__global__ void wa_kernel(const float* __restrict__ W,
                          const float* __restrict__ a_src,
                          const float* __restrict__ a_dst) {
    __shared__ float as[128], ad[128];
    int t = threadIdx.x;  // 128
    as[t] = a_src[t];
    ad[t] = a_dst[t];
    __syncthreads();
    int k = t;
    #pragma unroll
    for (int h = 0; h < 8; h++) {
        float s = 0.f, d = 0.f;
        #pragma unroll
        for (int c = 0; c < 16; c++) {
            float w = W[k * 128 + h * 16 + c];
            s += w * as[h * 16 + c];
            d += w * ad[h * 16 + c];
        }
        g_wa[k * 16 + h]     = s;
        g_wa[k * 16 + 8 + h] = d;
    }
}

// ---------------- GEMM: [rows x 128] @ [128 x 144] -> h, alpha_s, alpha_d ----
// W stored TRANSPOSED in smem (k contiguous) so that k-pairs load as LDS.64 and
// the inner product runs on packed fma.rn.f32x2 (even-k lane / odd-k lane).
#define KST 130   // k-stride for transposed W: even (8B-aligned LDS.64), bank-clean
#define XST 132
#define GEMM_SMEM ((144 * KST + 64 * XST) * 4)   // 108672 B

__global__ void __launch_bounds__(256, 2)
gemm_kernel(const float* __restrict__ X, const float* __restrict__ W) {
    extern __shared__ float sm[];
    float* Wsh = sm;                  // [144][KST]  (col-major: col c, then k)
    float* xs  = sm + 144 * KST;      // [64][XST]

    int tid = threadIdx.x;            // 256
    int row0 = blockIdx.x * 64;

    // load W (128x128) transposed: Wsh[c*KST + k] = W[k*128 + c]
    for (int i = tid * 4; i < 128 * 128; i += 1024) {
        float4 w = *(const float4*)(W + i);
        int k = i >> 7, c = i & 127;
        Wsh[(c + 0) * KST + k] = w.x;
        Wsh[(c + 1) * KST + k] = w.y;
        Wsh[(c + 2) * KST + k] = w.z;
        Wsh[(c + 3) * KST + k] = w.w;
    }
    // wa cols 128..143: Wsh[(128+j)*KST + k] = g_wa[k*16 + j]
    for (int i = tid; i < 128 * 16; i += 256) {
        int k = i >> 4, j = i & 15;
        Wsh[(128 + j) * KST + k] = g_wa[i];
    }
    // load X rows
    for (int i = tid * 4; i < 64 * 128; i += 1024) {
        int r = i >> 7, c = i & 127;
        int gr = row0 + r;
        float4 v = make_float4(0.f, 0.f, 0.f, 0.f);
        if (gr < NN) v = *(const float4*)(X + gr * FEAT + c);
        *(float4*)(xs + r * XST + c) = v;
    }
    __syncthreads();

    int ty = tid >> 4, tx = tid & 15;   // 16x16; thread tile 4 rows x 9 cols
    ull acc[4][9];
    #pragma unroll
    for (int i = 0; i < 4; i++)
        #pragma unroll
        for (int j = 0; j < 9; j++) acc[i][j] = 0ull;  // (0.f, 0.f)

    const float* xr0 = xs + (ty * 4 + 0) * XST;
    const float* xr1 = xs + (ty * 4 + 1) * XST;
    const float* xr2 = xs + (ty * 4 + 2) * XST;
    const float* xr3 = xs + (ty * 4 + 3) * XST;
    const float* wc  = Wsh + tx * KST;   // cols tx + 16*j  ->  + j*16*KST

    #pragma unroll 4
    for (int k = 0; k < 128; k += 2) {
        ull a0 = *(const ull*)(xr0 + k);
        ull a1 = *(const ull*)(xr1 + k);
        ull a2 = *(const ull*)(xr2 + k);
        ull a3 = *(const ull*)(xr3 + k);
        #pragma unroll
        for (int j = 0; j < 9; ++j) {
            ull b = *(const ull*)(wc + j * (16 * KST) + k);
            ffma2(acc[0][j], a0, b);
            ffma2(acc[1][j], a1, b);
            ffma2(acc[2][j], a2, b);
            ffma2(acc[3][j], a3, b);
        }
    }

    #pragma unroll
    for (int i = 0; i < 4; ++i) {
        int gr = row0 + ty * 4 + i;
        if (gr >= NN) continue;
        float* hrow = g_h + gr * HID;
        float res[9];
        #pragma unroll
        for (int j = 0; j < 9; ++j) {
            float lo, hi;
            asm("mov.b64 {%0, %1}, %2;" : "=f"(lo), "=f"(hi) : "l"(acc[i][j]));
            res[j] = lo + hi;
        }
        #pragma unroll
        for (int j = 0; j < 8; ++j) hrow[tx + 16 * j] = res[j];
        if (tx < 8) g_as[gr * 8 + tx]     = res[8];
        else        g_ad[gr * 8 + tx - 8] = res[8];
    }
}

// ---------------- fused GAT aggregation: warp per dst node -----------------
// out[d,:] = elu( (sum_e exp(lrelu(as[src]+ad[d])) * h[src]) / sum_e exp(...) + b )
__global__ void msg_kernel(const float* __restrict__ bias, float* __restrict__ out) {
    int gwarp = (blockIdx.x * blockDim.x + threadIdx.x) >> 5;
    int lane = threadIdx.x & 31;
    if (gwarp >= NN) return;
    int d = gwarp;
    int head = lane >> 2;                    // 4 lanes per head (16 dims / 4)
    float ad_h = g_ad[d * 8 + head];
    int beg = g_off[d], end = g_off[d + 1];
    int col = lane << 2;

    float4 acc = make_float4(0.f, 0.f, 0.f, 0.f);
    float ssum = 0.f;
    for (int i = beg; i < end; ++i) {
        int s = g_csr[i];
        float as_h = __ldg(&g_as[s * 8 + head]);
        float v = as_h + ad_h;
        v = (v > 0.f) ? v : 0.2f * v;        // leaky relu
        float e = __expf(v);
        float4 hv = *(const float4*)(g_h + s * 128 + col);
        acc.x += e * hv.x;
        acc.y += e * hv.y;
        acc.z += e * hv.z;
        acc.w += e * hv.w;
        ssum += e;
    }
    float inv = 1.f / (ssum + 1e-16f);
    float4 bb = *(const float4*)(bias + col);
    float4 o;
    float t;
    t = acc.x * inv + bb.x; o.x = (t > 0.f) ? t : expm1f(t);
    t = acc.y * inv + bb.y; o.y = (t > 0.f) ? t : expm1f(t);
    t = acc.z * inv + bb.z; o.z = (t > 0.f) ? t : expm1f(t);
    t = acc.w * inv + bb.w; o.w = (t > 0.f) ? t : expm1f(t);
    *(float4*)(out + d * 128 + col) = o;
}

// ---------------- launch ----------------
extern "C" void kernel_launch(void* const* d_in, const int* in_sizes, int n_in,
                              void* d_out, int out_size) {
    const float* x   = (const float*)d_in[0];
    const int*   ei  = (const int*)  d_in[1];
    const float* W1  = (const float*)d_in[2];
    const float* as1 = (const float*)d_in[3];
    const float* ad1 = (const float*)d_in[4];
    const float* b1  = (const float*)d_in[5];
    const float* W2  = (const float*)d_in[6];
    const float* as2 = (const float*)d_in[7];
    const float* ad2 = (const float*)d_in[8];
    const float* b2  = (const float*)d_in[9];
    float* out = (float*)d_out;

    cudaFuncSetAttribute(gemm_kernel,
                         cudaFuncAttributeMaxDynamicSharedMemorySize, GEMM_SMEM);

    void* p_x2 = nullptr;
    cudaGetSymbolAddress(&p_x2, g_x2);
    float* x2 = (float*)p_x2;

    // CSR build (graph identical for both layers)
    zero_kernel   <<<(NN + 255) / 256, 256>>>();
    count_kernel  <<<(E_TOT + 255) / 256, 256>>>(ei);
    scan_kernel   <<<1, 1024>>>();
    scatter_kernel<<<(E_TOT + 255) / 256, 256>>>(ei);

    int gemm_grid = (NN + 63) / 64;
    int msg_grid  = (NN * 32 + 255) / 256;

    // layer 1
    wa_kernel  <<<1, 128>>>(W1, as1, ad1);
    gemm_kernel<<<gemm_grid, 256, GEMM_SMEM>>>(x, W1);
    msg_kernel <<<msg_grid, 256>>>(b1, x2);              // fused bias + elu

    // layer 2
    wa_kernel  <<<1, 128>>>(W2, as2, ad2);
    gemm_kernel<<<gemm_grid, 256, GEMM_SMEM>>>(x2, W2);
    msg_kernel <<<msg_grid, 256>>>(b2, out);             // fused bias + elu -> final
}